// round 6
// baseline (speedup 1.0000x reference)
#include <cuda_runtime.h>
#include <math.h>

#define BB 64
#define TT 512
#define DD 512
#define HH 1024

#define NCTA    128
#define NTHR    512
#define JB      16          // j columns per CTA
#define BHALF   32          // batch rows per CTA
#define HSS     132         // hs row stride in floats (16B-aligned, odd /4 -> conflict-free)
#define CHUNK_K 128         // k per staged chunk
#define NCHUNK  (HH / CHUNK_K)
#define NKQ     (HH / 4)    // 256 k-quads total
#define KQ_CHUNK (CHUNK_K / 4)   // 32 k-quads per chunk

#define WS_FLOATS (3 * NKQ * JB * 4)          // 49152 (192 KB)
#define HS_FLOATS (BHALF * HSS)               // 4224  (16.5 KB)
#define SMEM_BYTES ((WS_FLOATS + HS_FLOATS) * 4)

typedef unsigned long long u64;

// Scratch (static device globals — allocation-free kernel_launch)
__device__ float g_XG[3 * TT * BB * HH];   // [g][t][b][h] x-projections (+ input bias)
__device__ float g_h[2][BB * HH];          // ping-pong hidden state
__device__ unsigned int g_bar_count = 0;
__device__ unsigned int g_bar_gen = 0;

__device__ __forceinline__ void ffma2(u64& d, u64 a, u64 b) {
    asm("fma.rn.f32x2 %0, %1, %2, %0;" : "+l"(d) : "l"(a), "l"(b));
}
__device__ __forceinline__ float pairsum(u64 v) {
    return __uint_as_float((unsigned)(v & 0xffffffffull)) +
           __uint_as_float((unsigned)(v >> 32));
}
__device__ __forceinline__ u64 splat2(float a) {
    u64 r;
    asm("mov.b64 %0, {%1, %1};" : "=l"(r) : "f"(a));
    return r;
}

// All 128 CTAs co-resident (1 CTA/SM) -> spin barrier safe. acq/rel semantics.
__device__ __forceinline__ void grid_barrier() {
    __syncthreads();
    if (threadIdx.x == 0) {
        unsigned gen;
        asm volatile("ld.relaxed.gpu.global.u32 %0, [%1];" : "=r"(gen) : "l"(&g_bar_gen));
        unsigned old;
        asm volatile("atom.acq_rel.gpu.global.add.u32 %0, [%1], 1;" : "=r"(old) : "l"(&g_bar_count));
        if (old == NCTA - 1) {
            asm volatile("st.relaxed.gpu.global.u32 [%0], %1;" :: "l"(&g_bar_count), "r"(0u));
            asm volatile("st.release.gpu.global.u32 [%0], %1;" :: "l"(&g_bar_gen), "r"(gen + 1));
        } else {
            unsigned cur;
            do {
                asm volatile("ld.acquire.gpu.global.u32 %0, [%1];" : "=r"(cur) : "l"(&g_bar_gen));
            } while (cur == gen);
        }
    }
    __syncthreads();
}

// ---------------------------------------------------------------------------
// Precompute xg[g][t][b][:] = x[b][t][:] @ W_gx + b_gx  (128x128x16, FFMA2)
// ---------------------------------------------------------------------------
__global__ __launch_bounds__(256) void xproj_kernel(
    const float* __restrict__ x,
    const float* __restrict__ Wz, const float* __restrict__ Wr, const float* __restrict__ Wn,
    const float* __restrict__ bz, const float* __restrict__ br, const float* __restrict__ bn) {

    int g = blockIdx.z;
    const float* Wm   = (g == 0) ? Wz : ((g == 1) ? Wr : Wn);
    const float* bias = (g == 0) ? bz : ((g == 1) ? br : bn);

    __shared__ float As[16][128];   // [k][m]
    __shared__ float Bs[16][128];   // [k][n]

    int m0 = blockIdx.x * 128;
    int n0 = blockIdx.y * 128;
    int tid = threadIdx.x;
    int txq = tid % 16, tyq = tid / 16;

    u64 acc2[4][8];
#pragma unroll
    for (int i = 0; i < 4; i++)
#pragma unroll
        for (int j = 0; j < 8; j++) acc2[i][j] = 0ull;

    for (int k0 = 0; k0 < DD; k0 += 16) {
#pragma unroll
        for (int l = 0; l < 2; l++) {
            int idx = tid + l * 256;
            int row = idx >> 2;
            int kk  = (idx & 3) * 4;
            float4 v = *(const float4*)&x[(size_t)(m0 + row) * DD + k0 + kk];
            As[kk + 0][row] = v.x;
            As[kk + 1][row] = v.y;
            As[kk + 2][row] = v.z;
            As[kk + 3][row] = v.w;
        }
#pragma unroll
        for (int l = 0; l < 2; l++) {
            int idx = tid + l * 256;
            int row = idx >> 5;
            int nn  = (idx & 31) * 4;
            *(float4*)&Bs[row][nn] = *(const float4*)&Wm[(size_t)(k0 + row) * HH + n0 + nn];
        }
        __syncthreads();
#pragma unroll
        for (int k = 0; k < 16; k++) {
            const u64* Ap = (const u64*)&As[k][tyq * 8];
            u64 ap0 = Ap[0], ap1 = Ap[1], ap2 = Ap[2], ap3 = Ap[3];
            float4 b0 = *(const float4*)&Bs[k][txq * 8];
            float4 b1 = *(const float4*)&Bs[k][txq * 8 + 4];
            u64 bs[8];
            bs[0] = splat2(b0.x); bs[1] = splat2(b0.y); bs[2] = splat2(b0.z); bs[3] = splat2(b0.w);
            bs[4] = splat2(b1.x); bs[5] = splat2(b1.y); bs[6] = splat2(b1.z); bs[7] = splat2(b1.w);
#pragma unroll
            for (int j = 0; j < 8; j++) {
                ffma2(acc2[0][j], ap0, bs[j]);
                ffma2(acc2[1][j], ap1, bs[j]);
                ffma2(acc2[2][j], ap2, bs[j]);
                ffma2(acc2[3][j], ap3, bs[j]);
            }
        }
        __syncthreads();
    }

#pragma unroll
    for (int ip = 0; ip < 4; ip++) {
#pragma unroll
        for (int half = 0; half < 2; half++) {
            int m  = m0 + tyq * 8 + ip * 2 + half;
            int bbv = m / TT;
            int tt = m % TT;
            float* outr = &g_XG[(((size_t)g * TT + tt) * BB + bbv) * HH + n0 + txq * 8];
#pragma unroll
            for (int j = 0; j < 8; j++) {
                u64 v = acc2[ip][j];
                float f = half ? __uint_as_float((unsigned)(v >> 32))
                               : __uint_as_float((unsigned)(v & 0xffffffffull));
                outr[j] = f + bias[n0 + txq * 8 + j];
            }
        }
    }
}

// ---------------------------------------------------------------------------
// Persistent GRU scan. 128 CTAs = 64 j-blocks x 2 batch-halves, 512 threads.
// Thread = (1 j, 1 row, 3 gates). Warp = 4 j x 8 rows; 16 warps = 4/SMSP.
// W resident in SMEM for all 512 steps; h staged per 128-k chunk.
// ---------------------------------------------------------------------------
__global__ __launch_bounds__(NTHR, 1) void gru_scan_kernel(
    float* __restrict__ out,
    const float* __restrict__ Wzh, const float* __restrict__ Wrh, const float* __restrict__ Wnh,
    const float* __restrict__ bzh, const float* __restrict__ brh, const float* __restrict__ bnh)
{
    extern __shared__ float smem[];
    float* ws = smem;                    // [g][kq][j][4]  (k-quad per float4)
    float* hs = smem + WS_FLOATS;        // [b_local][HSS]

    const int tid  = threadIdx.x;
    const int jb   = blockIdx.x & 63;
    const int bb   = blockIdx.x >> 6;
    const int warp = tid >> 5;
    const int lane = tid & 31;

    const int jq   = warp & 3;           // j-quad of this warp
    const int rh   = warp >> 2;          // row-octet of this warp (0..3)
    const int jl   = lane & 3;
    const int rl   = lane >> 2;          // 0..7
    const int j    = jq * 4 + jl;        // 0..15
    const int rloc = rh * 8 + rl;        // 0..31
    const int jcol = jb * JB + j;
    const int row  = bb * BHALF + rloc;  // global batch row

    // ---- load this CTA's W slice into SMEM (once) ----
    for (int e = tid; e < 3 * HH * JB; e += NTHR) {
        int jj = e & (JB - 1);
        int k  = (e >> 4) & (HH - 1);
        int g  = e >> 14;
        const float* Wsrc = (g == 0) ? Wzh : ((g == 1) ? Wrh : Wnh);
        ws[((g * NKQ + (k >> 2)) * JB + jj) * 4 + (k & 3)] =
            Wsrc[(size_t)k * HH + jb * JB + jj];
    }
    // ---- zero h[0] (disjoint slices) ----
    for (int e = tid; e < (BB * HH) / NCTA; e += NTHR)
        g_h[0][blockIdx.x * ((BB * HH) / NCTA) + e] = 0.0f;
    grid_barrier();

    const float bz = bzh[jcol], br = brh[jcol], bn = bnh[jcol];
    const ulonglong2* ws2 = (const ulonglong2*)ws;

    for (int t = 0; t < TT; t++) {
        const float* __restrict__ h_in  = g_h[t & 1];
        float* __restrict__ h_out = (t == TT - 1) ? out : g_h[(t + 1) & 1];

        // epilogue operands prefetched at step start
        const float* xz = g_XG + ((size_t)(0 * TT + t)) * (BB * HH);
        const float* xr = g_XG + ((size_t)(1 * TT + t)) * (BB * HH);
        const float* xn = g_XG + ((size_t)(2 * TT + t)) * (BB * HH);
        float xzv = __ldg(&xz[(size_t)row * HH + jcol]);
        float xrv = __ldg(&xr[(size_t)row * HH + jcol]);
        float xnv = __ldg(&xn[(size_t)row * HH + jcol]);
        float hpv = __ldcg(&h_in[(size_t)row * HH + jcol]);

        u64 az = 0, ar = 0, an = 0;

        // register-double-buffered h staging: 2 float4 per thread per chunk
        float4 pf[2];
        {
#pragma unroll
            for (int l = 0; l < 2; l++) {
                int idx = tid + l * NTHR;   // 1024 float4 per chunk
                int rw  = idx >> 5;
                int c   = idx & 31;
                pf[l] = __ldcg((const float4*)&h_in[(size_t)(bb * BHALF + rw) * HH + c * 4]);
            }
        }

        for (int ch = 0; ch < NCHUNK; ch++) {
            __syncthreads();
#pragma unroll
            for (int l = 0; l < 2; l++) {
                int idx = tid + l * NTHR;
                int rw  = idx >> 5;
                int c   = idx & 31;
                *(float4*)&hs[rw * HSS + c * 4] = pf[l];
            }
            __syncthreads();
            if (ch + 1 < NCHUNK) {
                const int kcn = (ch + 1) * CHUNK_K;
#pragma unroll
                for (int l = 0; l < 2; l++) {
                    int idx = tid + l * NTHR;
                    int rw  = idx >> 5;
                    int c   = idx & 31;
                    pf[l] = __ldcg((const float4*)&h_in[(size_t)(bb * BHALF + rw) * HH + kcn + c * 4]);
                }
            }

            const int kq0 = ch * KQ_CHUNK;
            const ulonglong2* hp = (const ulonglong2*)(hs + rloc * HSS);
            const ulonglong2* wzp = ws2 + ((size_t)(0 * NKQ + kq0) * JB + j);
            const ulonglong2* wrp = ws2 + ((size_t)(1 * NKQ + kq0) * JB + j);
            const ulonglong2* wnp = ws2 + ((size_t)(2 * NKQ + kq0) * JB + j);

#pragma unroll
            for (int kql = 0; kql < KQ_CHUNK; kql++) {
                ulonglong2 ha  = hp[kql];
                ulonglong2 wz  = wzp[(size_t)kql * JB];
                ulonglong2 wr2 = wrp[(size_t)kql * JB];
                ulonglong2 wn2 = wnp[(size_t)kql * JB];
                ffma2(az, ha.x, wz.x);  ffma2(az, ha.y, wz.y);
                ffma2(ar, ha.x, wr2.x); ffma2(ar, ha.y, wr2.y);
                ffma2(an, ha.x, wn2.x); ffma2(an, ha.y, wn2.y);
            }
        }

        float hz = pairsum(az);
        float hr = pairsum(ar);
        float hn = pairsum(an);

        {
            float z = 1.0f / (1.0f + __expf(-(xzv + hz + bz)));
            float r = 1.0f / (1.0f + __expf(-(xrv + hr + br)));
            float n = tanhf(xnv + r * (hn + bn));
            __stcg(&h_out[(size_t)row * HH + jcol], (1.0f - z) * n + z * hpv);
        }

        if (t != TT - 1) grid_barrier();
    }
}

// ---------------------------------------------------------------------------
extern "C" void kernel_launch(void* const* d_in, const int* in_sizes, int n_in,
                              void* d_out, int out_size) {
    const float* x    = (const float*)d_in[0];
    const float* W_zx = (const float*)d_in[1];
    const float* W_zh = (const float*)d_in[2];
    const float* W_rx = (const float*)d_in[3];
    const float* W_rh = (const float*)d_in[4];
    const float* W_nx = (const float*)d_in[5];
    const float* W_nh = (const float*)d_in[6];
    const float* b_zx = (const float*)d_in[7];
    const float* b_zh = (const float*)d_in[8];
    const float* b_rx = (const float*)d_in[9];
    const float* b_rh = (const float*)d_in[10];
    const float* b_nx = (const float*)d_in[11];
    const float* b_nh = (const float*)d_in[12];
    float* out = (float*)d_out;

    cudaFuncSetAttribute(gru_scan_kernel,
                         cudaFuncAttributeMaxDynamicSharedMemorySize, SMEM_BYTES);

    xproj_kernel<<<dim3((BB * TT) / 128, HH / 128, 3), 256>>>(
        x, W_zx, W_rx, W_nx, b_zx, b_rx, b_nx);

    gru_scan_kernel<<<NCTA, NTHR, SMEM_BYTES>>>(
        out, W_zh, W_rh, W_nh, b_zh, b_rh, b_nh);
}

// round 7
// speedup vs baseline: 1.3910x; 1.3910x over previous
#include <cuda_runtime.h>
#include <math.h>

#define BB 64
#define TT 512
#define DD 512
#define HH 1024

#define NCTA 128
#define NTHR 256
#define JB   8              // j columns per CTA
#define NROW 64             // all batch rows per CTA
#define CHUNK_K 128
#define NCHUNK (HH / CHUNK_K)    // 8
#define HSS   132                // staged h row stride (floats)
#define HSBUF (NROW * HSS)       // 8448 floats per buffer
#define NKQ   (HH / 4)           // 256 k-quads
#define KQ_CH (CHUNK_K / 4)      // 32 k-quads per chunk

#define WS_FLOATS (3 * NKQ * JB * 4)              // 24576 (96 KB)
#define SMEM_FLOATS (WS_FLOATS + 2 * HSBUF)       // 41472 (162 KB)
#define SMEM_BYTES (SMEM_FLOATS * 4)

typedef unsigned long long u64;

// Scratch (static device globals — allocation-free kernel_launch)
__device__ float g_XG[3 * TT * BB * HH];   // [g][t][b][h] x-projections (+ input bias)
__device__ float g_h[2][BB * HH];          // ping-pong hidden state
__device__ unsigned int g_bar_count = 0;
__device__ unsigned int g_bar_gen = 0;

__device__ __forceinline__ void ffma2(u64& d, u64 a, u64 b) {
    asm("fma.rn.f32x2 %0, %1, %2, %0;" : "+l"(d) : "l"(a), "l"(b));
}
__device__ __forceinline__ float pairsum(u64 v) {
    return __uint_as_float((unsigned)(v & 0xffffffffull)) +
           __uint_as_float((unsigned)(v >> 32));
}
__device__ __forceinline__ u64 splat2(float a) {
    u64 r;
    asm("mov.b64 %0, {%1, %1};" : "=l"(r) : "f"(a));
    return r;
}
__device__ __forceinline__ unsigned smem_u32(const void* p) {
    return (unsigned)__cvta_generic_to_shared(p);
}
// 16B async copy global->smem, L1-bypass (.cg) — h is produced by other SMs.
__device__ __forceinline__ void cp_async16(unsigned dst, const void* src) {
    asm volatile("cp.async.cg.shared.global [%0], [%1], 16;" :: "r"(dst), "l"(src));
}
__device__ __forceinline__ void cp_commit() {
    asm volatile("cp.async.commit_group;");
}
template <int N>
__device__ __forceinline__ void cp_wait() {
    asm volatile("cp.async.wait_group %0;" :: "n"(N));
}

// All 128 CTAs co-resident (1 CTA/SM) -> spin barrier safe. acq/rel semantics.
__device__ __forceinline__ void grid_barrier() {
    __syncthreads();
    if (threadIdx.x == 0) {
        unsigned gen;
        asm volatile("ld.relaxed.gpu.global.u32 %0, [%1];" : "=r"(gen) : "l"(&g_bar_gen));
        unsigned old;
        asm volatile("atom.acq_rel.gpu.global.add.u32 %0, [%1], 1;" : "=r"(old) : "l"(&g_bar_count));
        if (old == NCTA - 1) {
            asm volatile("st.relaxed.gpu.global.u32 [%0], %1;" :: "l"(&g_bar_count), "r"(0u));
            asm volatile("st.release.gpu.global.u32 [%0], %1;" :: "l"(&g_bar_gen), "r"(gen + 1));
        } else {
            unsigned cur;
            do {
                asm volatile("ld.acquire.gpu.global.u32 %0, [%1];" : "=r"(cur) : "l"(&g_bar_gen));
            } while (cur == gen);
        }
    }
    __syncthreads();
}

// ---------------------------------------------------------------------------
// Precompute xg[g][t][b][:] = x[b][t][:] @ W_gx + b_gx  (128x128x16, FFMA2)
// ---------------------------------------------------------------------------
__global__ __launch_bounds__(256) void xproj_kernel(
    const float* __restrict__ x,
    const float* __restrict__ Wz, const float* __restrict__ Wr, const float* __restrict__ Wn,
    const float* __restrict__ bz, const float* __restrict__ br, const float* __restrict__ bn) {

    int g = blockIdx.z;
    const float* Wm   = (g == 0) ? Wz : ((g == 1) ? Wr : Wn);
    const float* bias = (g == 0) ? bz : ((g == 1) ? br : bn);

    __shared__ float As[16][128];   // [k][m]
    __shared__ float Bs[16][128];   // [k][n]

    int m0 = blockIdx.x * 128;
    int n0 = blockIdx.y * 128;
    int tid = threadIdx.x;
    int txq = tid % 16, tyq = tid / 16;

    u64 acc2[4][8];
#pragma unroll
    for (int i = 0; i < 4; i++)
#pragma unroll
        for (int j = 0; j < 8; j++) acc2[i][j] = 0ull;

    for (int k0 = 0; k0 < DD; k0 += 16) {
#pragma unroll
        for (int l = 0; l < 2; l++) {
            int idx = tid + l * 256;
            int row = idx >> 2;
            int kk  = (idx & 3) * 4;
            float4 v = *(const float4*)&x[(size_t)(m0 + row) * DD + k0 + kk];
            As[kk + 0][row] = v.x;
            As[kk + 1][row] = v.y;
            As[kk + 2][row] = v.z;
            As[kk + 3][row] = v.w;
        }
#pragma unroll
        for (int l = 0; l < 2; l++) {
            int idx = tid + l * 256;
            int row = idx >> 5;
            int nn  = (idx & 31) * 4;
            *(float4*)&Bs[row][nn] = *(const float4*)&Wm[(size_t)(k0 + row) * HH + n0 + nn];
        }
        __syncthreads();
#pragma unroll
        for (int k = 0; k < 16; k++) {
            const u64* Ap = (const u64*)&As[k][tyq * 8];
            u64 ap0 = Ap[0], ap1 = Ap[1], ap2 = Ap[2], ap3 = Ap[3];
            float4 b0 = *(const float4*)&Bs[k][txq * 8];
            float4 b1 = *(const float4*)&Bs[k][txq * 8 + 4];
            u64 bs[8];
            bs[0] = splat2(b0.x); bs[1] = splat2(b0.y); bs[2] = splat2(b0.z); bs[3] = splat2(b0.w);
            bs[4] = splat2(b1.x); bs[5] = splat2(b1.y); bs[6] = splat2(b1.z); bs[7] = splat2(b1.w);
#pragma unroll
            for (int j = 0; j < 8; j++) {
                ffma2(acc2[0][j], ap0, bs[j]);
                ffma2(acc2[1][j], ap1, bs[j]);
                ffma2(acc2[2][j], ap2, bs[j]);
                ffma2(acc2[3][j], ap3, bs[j]);
            }
        }
        __syncthreads();
    }

#pragma unroll
    for (int ip = 0; ip < 4; ip++) {
#pragma unroll
        for (int half = 0; half < 2; half++) {
            int m  = m0 + tyq * 8 + ip * 2 + half;
            int bbv = m / TT;
            int tt = m % TT;
            float* outr = &g_XG[(((size_t)g * TT + tt) * BB + bbv) * HH + n0 + txq * 8];
#pragma unroll
            for (int j = 0; j < 8; j++) {
                u64 v = acc2[ip][j];
                float f = half ? __uint_as_float((unsigned)(v >> 32))
                               : __uint_as_float((unsigned)(v & 0xffffffffull));
                outr[j] = f + bias[n0 + txq * 8 + j];
            }
        }
    }
}

// ---------------------------------------------------------------------------
// Persistent GRU scan. 128 CTAs x 8 j-cols x 64 rows. 256 threads = 8 warps.
// Thread = (1 j, 2 rows, 3 gates). W resident in SMEM (96 KB); h staged in
// double-buffered SMEM chunks via cp.async.cg (no staging registers).
// Inner loop: pure LDS.128 + fma.rn.f32x2 with immediate offsets.
// ---------------------------------------------------------------------------
__global__ __launch_bounds__(NTHR, 1) void gru_scan_kernel(
    float* __restrict__ out,
    const float* __restrict__ Wzh, const float* __restrict__ Wrh, const float* __restrict__ Wnh,
    const float* __restrict__ bzh, const float* __restrict__ brh, const float* __restrict__ bnh)
{
    extern __shared__ float smem[];
    float* ws = smem;                       // [g][kq][j][4]
    float* hs0 = smem + WS_FLOATS;          // staging buffer 0
    float* hs1 = hs0 + HSBUF;               // staging buffer 1

    const int tid  = threadIdx.x;
    const int jbk  = blockIdx.x;            // j-block 0..127
    const int jl   = tid & 7;
    const int brr  = tid >> 3;              // 0..31
    const int b0   = brr;
    const int b1   = brr + 32;
    const int jcol = jbk * JB + jl;

    // ---- load this CTA's W slice into SMEM (once) ----
    for (int e = tid; e < 3 * HH * JB; e += NTHR) {
        int jj = e & (JB - 1);
        int k  = (e >> 3) & (HH - 1);
        int g  = e >> 13;
        const float* Wsrc = (g == 0) ? Wzh : ((g == 1) ? Wrh : Wnh);
        ws[((g * NKQ + (k >> 2)) * JB + jj) * 4 + (k & 3)] =
            Wsrc[(size_t)k * HH + jbk * JB + jj];
    }
    // ---- zero h[0] (disjoint slices) ----
    for (int e = tid; e < (BB * HH) / NCTA; e += NTHR)
        g_h[0][blockIdx.x * ((BB * HH) / NCTA) + e] = 0.0f;
    grid_barrier();

    const float bz = bzh[jcol], br = brh[jcol], bn = bnh[jcol];
    const ulonglong2* ws2 = (const ulonglong2*)ws;

    // staging assignment: per chunk, thread copies 8 float4
    const int srow = tid >> 5;              // rows srow, srow+32, ... pattern below
    const int scol = tid & 31;              // float4 column within 128-k chunk

    for (int t = 0; t < TT; t++) {
        const float* __restrict__ h_in  = g_h[t & 1];
        float* __restrict__ h_out = (t == TT - 1) ? out : g_h[(t + 1) & 1];

        // epilogue operands prefetched at step start (consumed after K loop)
        const float* xz = g_XG + ((size_t)(0 * TT + t)) * (BB * HH);
        const float* xr = g_XG + ((size_t)(1 * TT + t)) * (BB * HH);
        const float* xn = g_XG + ((size_t)(2 * TT + t)) * (BB * HH);
        float xz0 = __ldg(&xz[(size_t)b0 * HH + jcol]), xz1 = __ldg(&xz[(size_t)b1 * HH + jcol]);
        float xr0 = __ldg(&xr[(size_t)b0 * HH + jcol]), xr1 = __ldg(&xr[(size_t)b1 * HH + jcol]);
        float xn0 = __ldg(&xn[(size_t)b0 * HH + jcol]), xn1 = __ldg(&xn[(size_t)b1 * HH + jcol]);
        float hp0 = __ldcg(&h_in[(size_t)b0 * HH + jcol]);
        float hp1 = __ldcg(&h_in[(size_t)b1 * HH + jcol]);

        u64 az0 = 0, az1 = 0, ar0 = 0, ar1 = 0, an0 = 0, an1 = 0;

        // ---- prologue: stage chunk 0 into hs0 ----
        {
            float* buf = hs0;
#pragma unroll
            for (int l = 0; l < 8; l++) {
                int row = srow + l * 8;
                cp_async16(smem_u32(&buf[row * HSS + scol * 4]),
                           &h_in[(size_t)row * HH + scol * 4]);
            }
            cp_commit();
        }

        for (int ch = 0; ch < NCHUNK; ch++) {
            // issue next chunk into the other buffer (freed by trailing sync of ch-1)
            if (ch + 1 < NCHUNK) {
                float* buf = ((ch + 1) & 1) ? hs1 : hs0;
                const int kcn = (ch + 1) * CHUNK_K;
#pragma unroll
                for (int l = 0; l < 8; l++) {
                    int row = srow + l * 8;
                    cp_async16(smem_u32(&buf[row * HSS + kcn + scol * 4]) - smem_u32(&buf[0]) + smem_u32(&buf[0]) - kcn * 4,
                               &h_in[(size_t)row * HH + kcn + scol * 4]);
                }
                cp_commit();
                cp_wait<1>();
            } else {
                cp_wait<0>();
            }
            __syncthreads();    // chunk ch data visible to all

            const float* buf = (ch & 1) ? hs1 : hs0;
            const ulonglong2* h0p = (const ulonglong2*)(buf + b0 * HSS);
            const ulonglong2* h1p = (const ulonglong2*)(buf + b1 * HSS);
            const ulonglong2* wb  = ws2 + (size_t)(ch * KQ_CH) * JB + jl;

#pragma unroll
            for (int i = 0; i < KQ_CH / 2; i++) {
                ulonglong2 h00 = h0p[2 * i],     h01 = h0p[2 * i + 1];
                ulonglong2 h10 = h1p[2 * i],     h11 = h1p[2 * i + 1];
                ulonglong2 wz0 = wb[(size_t)(2 * i) * JB];
                ulonglong2 wz1 = wb[(size_t)(2 * i + 1) * JB];
                ulonglong2 wr0 = wb[(size_t)(NKQ + 2 * i) * JB];
                ulonglong2 wr1 = wb[(size_t)(NKQ + 2 * i + 1) * JB];
                ulonglong2 wn0 = wb[(size_t)(2 * NKQ + 2 * i) * JB];
                ulonglong2 wn1 = wb[(size_t)(2 * NKQ + 2 * i + 1) * JB];

                ffma2(az0, h00.x, wz0.x); ffma2(az0, h00.y, wz0.y);
                ffma2(az0, h01.x, wz1.x); ffma2(az0, h01.y, wz1.y);
                ffma2(az1, h10.x, wz0.x); ffma2(az1, h10.y, wz0.y);
                ffma2(az1, h11.x, wz1.x); ffma2(az1, h11.y, wz1.y);

                ffma2(ar0, h00.x, wr0.x); ffma2(ar0, h00.y, wr0.y);
                ffma2(ar0, h01.x, wr1.x); ffma2(ar0, h01.y, wr1.y);
                ffma2(ar1, h10.x, wr0.x); ffma2(ar1, h10.y, wr0.y);
                ffma2(ar1, h11.x, wr1.x); ffma2(ar1, h11.y, wr1.y);

                ffma2(an0, h00.x, wn0.x); ffma2(an0, h00.y, wn0.y);
                ffma2(an0, h01.x, wn1.x); ffma2(an0, h01.y, wn1.y);
                ffma2(an1, h10.x, wn0.x); ffma2(an1, h10.y, wn0.y);
                ffma2(an1, h11.x, wn1.x); ffma2(an1, h11.y, wn1.y);
            }
            __syncthreads();    // chunk ch buffer free for reuse
        }

        float hz0 = pairsum(az0), hz1 = pairsum(az1);
        float hr0 = pairsum(ar0), hr1 = pairsum(ar1);
        float hn0 = pairsum(an0), hn1 = pairsum(an1);

        {
            float z = 1.0f / (1.0f + __expf(-(xz0 + hz0 + bz)));
            float r = 1.0f / (1.0f + __expf(-(xr0 + hr0 + br)));
            float n = tanhf(xn0 + r * (hn0 + bn));
            __stcg(&h_out[(size_t)b0 * HH + jcol], (1.0f - z) * n + z * hp0);
        }
        {
            float z = 1.0f / (1.0f + __expf(-(xz1 + hz1 + bz)));
            float r = 1.0f / (1.0f + __expf(-(xr1 + hr1 + br)));
            float n = tanhf(xn1 + r * (hn1 + bn));
            __stcg(&h_out[(size_t)b1 * HH + jcol], (1.0f - z) * n + z * hp1);
        }

        if (t != TT - 1) grid_barrier();
    }
}

// ---------------------------------------------------------------------------
extern "C" void kernel_launch(void* const* d_in, const int* in_sizes, int n_in,
                              void* d_out, int out_size) {
    const float* x    = (const float*)d_in[0];
    const float* W_zx = (const float*)d_in[1];
    const float* W_zh = (const float*)d_in[2];
    const float* W_rx = (const float*)d_in[3];
    const float* W_rh = (const float*)d_in[4];
    const float* W_nx = (const float*)d_in[5];
    const float* W_nh = (const float*)d_in[6];
    const float* b_zx = (const float*)d_in[7];
    const float* b_zh = (const float*)d_in[8];
    const float* b_rx = (const float*)d_in[9];
    const float* b_rh = (const float*)d_in[10];
    const float* b_nx = (const float*)d_in[11];
    const float* b_nh = (const float*)d_in[12];
    float* out = (float*)d_out;

    cudaFuncSetAttribute(gru_scan_kernel,
                         cudaFuncAttributeMaxDynamicSharedMemorySize, SMEM_BYTES);

    xproj_kernel<<<dim3((BB * TT) / 128, HH / 128, 3), 256>>>(
        x, W_zx, W_rx, W_nx, b_zx, b_rx, b_nx);

    gru_scan_kernel<<<NCTA, NTHR, SMEM_BYTES>>>(
        out, W_zh, W_rh, W_nh, b_zh, b_rh, b_nh);
}

// round 8
// speedup vs baseline: 1.5602x; 1.1216x over previous
#include <cuda_runtime.h>
#include <math.h>

#define BB 64
#define TT 512
#define DD 512
#define HH 1024

#define NCTA 128
#define NTHR 256
#define JB   8

// partials: [g][w][b][j] = 3 * 8 * 64 * 8 floats = 48 KB dynamic smem
#define PART_FLOATS (3 * 8 * BB * JB)
#define SMEM_BYTES (PART_FLOATS * 4)

typedef unsigned long long u64;

// Scratch (static device globals — allocation-free kernel_launch)
__device__ float g_XG[3 * TT * BB * HH];   // [g][t][b][h] x-projections (+ input bias)
__device__ float g_h[2][BB * HH];          // ping-pong hidden state
__device__ unsigned int g_bar_count = 0;
__device__ unsigned int g_bar_gen = 0;

__device__ __forceinline__ void ffma2(u64& d, u64 a, u64 b) {
    asm("fma.rn.f32x2 %0, %1, %2, %0;" : "+l"(d) : "l"(a), "l"(b));
}
__device__ __forceinline__ float pairsum(u64 v) {
    return __uint_as_float((unsigned)(v & 0xffffffffull)) +
           __uint_as_float((unsigned)(v >> 32));
}
__device__ __forceinline__ u64 pack2(float lo, float hi) {
    u64 r;
    asm("mov.b64 %0, {%1, %2};" : "=l"(r) : "f"(lo), "f"(hi));
    return r;
}
__device__ __forceinline__ u64 splat2(float a) {
    u64 r;
    asm("mov.b64 %0, {%1, %1};" : "=l"(r) : "f"(a));
    return r;
}

// All 128 CTAs co-resident (1 CTA/SM) -> spin barrier safe. acq/rel semantics.
__device__ __forceinline__ void grid_barrier() {
    __syncthreads();
    if (threadIdx.x == 0) {
        unsigned gen;
        asm volatile("ld.relaxed.gpu.global.u32 %0, [%1];" : "=r"(gen) : "l"(&g_bar_gen));
        unsigned old;
        asm volatile("atom.acq_rel.gpu.global.add.u32 %0, [%1], 1;" : "=r"(old) : "l"(&g_bar_count));
        if (old == NCTA - 1) {
            asm volatile("st.relaxed.gpu.global.u32 [%0], %1;" :: "l"(&g_bar_count), "r"(0u));
            asm volatile("st.release.gpu.global.u32 [%0], %1;" :: "l"(&g_bar_gen), "r"(gen + 1));
        } else {
            unsigned cur;
            do {
                asm volatile("ld.acquire.gpu.global.u32 %0, [%1];" : "=r"(cur) : "l"(&g_bar_gen));
            } while (cur == gen);
        }
    }
    __syncthreads();
}

// ---------------------------------------------------------------------------
// Precompute xg[g][t][b][:] = x[b][t][:] @ W_gx + b_gx  (128x128x16, FFMA2)
// ---------------------------------------------------------------------------
__global__ __launch_bounds__(256) void xproj_kernel(
    const float* __restrict__ x,
    const float* __restrict__ Wz, const float* __restrict__ Wr, const float* __restrict__ Wn,
    const float* __restrict__ bz, const float* __restrict__ br, const float* __restrict__ bn) {

    int g = blockIdx.z;
    const float* Wm   = (g == 0) ? Wz : ((g == 1) ? Wr : Wn);
    const float* bias = (g == 0) ? bz : ((g == 1) ? br : bn);

    __shared__ float As[16][128];   // [k][m]
    __shared__ float Bs[16][128];   // [k][n]

    int m0 = blockIdx.x * 128;
    int n0 = blockIdx.y * 128;
    int tid = threadIdx.x;
    int txq = tid % 16, tyq = tid / 16;

    u64 acc2[4][8];
#pragma unroll
    for (int i = 0; i < 4; i++)
#pragma unroll
        for (int j = 0; j < 8; j++) acc2[i][j] = 0ull;

    for (int k0 = 0; k0 < DD; k0 += 16) {
#pragma unroll
        for (int l = 0; l < 2; l++) {
            int idx = tid + l * 256;
            int row = idx >> 2;
            int kk  = (idx & 3) * 4;
            float4 v = *(const float4*)&x[(size_t)(m0 + row) * DD + k0 + kk];
            As[kk + 0][row] = v.x;
            As[kk + 1][row] = v.y;
            As[kk + 2][row] = v.z;
            As[kk + 3][row] = v.w;
        }
#pragma unroll
        for (int l = 0; l < 2; l++) {
            int idx = tid + l * 256;
            int row = idx >> 5;
            int nn  = (idx & 31) * 4;
            *(float4*)&Bs[row][nn] = *(const float4*)&Wm[(size_t)(k0 + row) * HH + n0 + nn];
        }
        __syncthreads();
#pragma unroll
        for (int k = 0; k < 16; k++) {
            const u64* Ap = (const u64*)&As[k][tyq * 8];
            u64 ap0 = Ap[0], ap1 = Ap[1], ap2 = Ap[2], ap3 = Ap[3];
            float4 b0 = *(const float4*)&Bs[k][txq * 8];
            float4 b1 = *(const float4*)&Bs[k][txq * 8 + 4];
            u64 bs[8];
            bs[0] = splat2(b0.x); bs[1] = splat2(b0.y); bs[2] = splat2(b0.z); bs[3] = splat2(b0.w);
            bs[4] = splat2(b1.x); bs[5] = splat2(b1.y); bs[6] = splat2(b1.z); bs[7] = splat2(b1.w);
#pragma unroll
            for (int j = 0; j < 8; j++) {
                ffma2(acc2[0][j], ap0, bs[j]);
                ffma2(acc2[1][j], ap1, bs[j]);
                ffma2(acc2[2][j], ap2, bs[j]);
                ffma2(acc2[3][j], ap3, bs[j]);
            }
        }
        __syncthreads();
    }

#pragma unroll
    for (int ip = 0; ip < 4; ip++) {
#pragma unroll
        for (int half = 0; half < 2; half++) {
            int m  = m0 + tyq * 8 + ip * 2 + half;
            int bbv = m / TT;
            int tt = m % TT;
            float* outr = &g_XG[(((size_t)g * TT + tt) * BB + bbv) * HH + n0 + txq * 8];
#pragma unroll
            for (int j = 0; j < 8; j++) {
                u64 v = acc2[ip][j];
                float f = half ? __uint_as_float((unsigned)(v >> 32))
                               : __uint_as_float((unsigned)(v & 0xffffffffull));
                outr[j] = f + bias[n0 + txq * 8 + j];
            }
        }
    }
}

// ---------------------------------------------------------------------------
// Persistent GRU scan, register-resident weights.
// 128 CTAs x 8 j-cols. 256 threads. Warp w owns k[128w,128w+128);
// lane = (j = l&7, ksub = l>>3). Thread holds W[3 gates][32 k] in 48 u64 regs.
// Per batch row: 8 LDG.128 (h from L2), 48 FFMA2, shfl-reduce over ksub,
// STS warp-partial. Cross-warp reduce + gate epilogue after one syncthreads.
// ---------------------------------------------------------------------------
__global__ __launch_bounds__(NTHR, 1) void gru_scan_kernel(
    float* __restrict__ out,
    const float* __restrict__ Wzh, const float* __restrict__ Wrh, const float* __restrict__ Wnh,
    const float* __restrict__ bzh, const float* __restrict__ brh, const float* __restrict__ bnh)
{
    extern __shared__ float part[];   // [g][w][b][j]: g*4096 + w*512 + b*8 + j

    const int tid  = threadIdx.x;
    const int jbk  = blockIdx.x;
    const int warp = tid >> 5;
    const int lane = tid & 31;
    const int jl   = lane & 7;
    const int ksub = lane >> 3;                 // 0..3
    const int kb   = warp * 128 + ksub * 32;    // thread's k-base (32 k's)
    const int pbase = warp * 512 + jl;          // partial store base

    // ---- W into registers: 16 pairs x 3 gates (held for all 512 steps) ----
    u64 wz[16], wr[16], wn[16];
    {
        const int jcolw = jbk * JB + jl;
#pragma unroll
        for (int p = 0; p < 16; p++) {
            int k = kb + 2 * p;
            wz[p] = pack2(__ldg(&Wzh[(size_t)k * HH + jcolw]), __ldg(&Wzh[(size_t)(k + 1) * HH + jcolw]));
            wr[p] = pack2(__ldg(&Wrh[(size_t)k * HH + jcolw]), __ldg(&Wrh[(size_t)(k + 1) * HH + jcolw]));
            wn[p] = pack2(__ldg(&Wnh[(size_t)k * HH + jcolw]), __ldg(&Wnh[(size_t)(k + 1) * HH + jcolw]));
        }
    }

    // ---- epilogue-side constants: thread handles output pairs tid, tid+256 ----
    int bq[2], jq[2], jc[2];
    float bzv[2], brv[2], bnv[2];
#pragma unroll
    for (int q = 0; q < 2; q++) {
        int p = tid + q * 256;
        bq[q] = p >> 3;
        jq[q] = p & 7;
        jc[q] = jbk * JB + jq[q];
        bzv[q] = __ldg(&bzh[jc[q]]);
        brv[q] = __ldg(&brh[jc[q]]);
        bnv[q] = __ldg(&bnh[jc[q]]);
    }

    // ---- zero h[0] (disjoint slices) ----
    for (int e = tid; e < (BB * HH) / NCTA; e += NTHR)
        g_h[0][blockIdx.x * ((BB * HH) / NCTA) + e] = 0.0f;
    grid_barrier();

#define LOADH(BUF, BV) do {                                                        \
        const float4* hp4_ = (const float4*)(h_in + (size_t)(BV) * HH + kb);       \
        _Pragma("unroll")                                                          \
        for (int i_ = 0; i_ < 8; i_++) (BUF)[i_] = __ldcg(hp4_ + i_);              \
    } while (0)

#define GRU_BODY(BUF, BV) do {                                                     \
        u64 az_ = 0, ar_ = 0, an_ = 0;                                             \
        const u64* hp_ = (const u64*)(BUF);                                        \
        _Pragma("unroll")                                                          \
        for (int p_ = 0; p_ < 16; p_++) {                                          \
            ffma2(az_, hp_[p_], wz[p_]);                                           \
            ffma2(ar_, hp_[p_], wr[p_]);                                           \
            ffma2(an_, hp_[p_], wn[p_]);                                           \
        }                                                                          \
        float zz_ = pairsum(az_), rr_ = pairsum(ar_), nn_ = pairsum(an_);          \
        zz_ += __shfl_xor_sync(0xffffffffu, zz_, 8);                               \
        zz_ += __shfl_xor_sync(0xffffffffu, zz_, 16);                              \
        rr_ += __shfl_xor_sync(0xffffffffu, rr_, 8);                               \
        rr_ += __shfl_xor_sync(0xffffffffu, rr_, 16);                              \
        nn_ += __shfl_xor_sync(0xffffffffu, nn_, 8);                               \
        nn_ += __shfl_xor_sync(0xffffffffu, nn_, 16);                              \
        if (ksub == 0) {                                                           \
            part[pbase + (BV) * 8]        = zz_;                                   \
            part[pbase + (BV) * 8 + 4096] = rr_;                                   \
            part[pbase + (BV) * 8 + 8192] = nn_;                                   \
        }                                                                          \
    } while (0)

    for (int t = 0; t < TT; t++) {
        const float* __restrict__ h_in  = g_h[t & 1];
        float* __restrict__ h_out = (t == TT - 1) ? out : g_h[(t + 1) & 1];

        // epilogue operand prefetch (consumed after the b-loop)
        const float* xz = g_XG + ((size_t)(0 * TT + t)) * (BB * HH);
        const float* xr = g_XG + ((size_t)(1 * TT + t)) * (BB * HH);
        const float* xn = g_XG + ((size_t)(2 * TT + t)) * (BB * HH);
        float xzp[2], xrp[2], xnp[2], hpv[2];
#pragma unroll
        for (int q = 0; q < 2; q++) {
            xzp[q] = __ldg(&xz[(size_t)bq[q] * HH + jc[q]]);
            xrp[q] = __ldg(&xr[(size_t)bq[q] * HH + jc[q]]);
            xnp[q] = __ldg(&xn[(size_t)bq[q] * HH + jc[q]]);
            hpv[q] = __ldcg(&h_in[(size_t)bq[q] * HH + jc[q]]);
        }

        // ---- main: 64 batch rows, software-pipelined by 2 ----
        float4 bufA[8], bufB[8];
        LOADH(bufA, 0);
        for (int b = 0; b < BB; b += 2) {
            LOADH(bufB, b + 1);
            GRU_BODY(bufA, b);
            if (b + 2 < BB) LOADH(bufA, b + 2);
            GRU_BODY(bufB, b + 1);
        }

        __syncthreads();

        // ---- cross-warp reduce + gate epilogue (2 outputs per thread) ----
#pragma unroll
        for (int q = 0; q < 2; q++) {
            int o = bq[q] * 8 + jq[q];
            float sz = 0.0f, sr = 0.0f, sn = 0.0f;
#pragma unroll
            for (int w = 0; w < 8; w++) {
                sz += part[w * 512 + o];
                sr += part[4096 + w * 512 + o];
                sn += part[8192 + w * 512 + o];
            }
            float z = 1.0f / (1.0f + __expf(-(xzp[q] + sz + bzv[q])));
            float r = 1.0f / (1.0f + __expf(-(xrp[q] + sr + brv[q])));
            float n = tanhf(xnp[q] + r * (sn + bnv[q]));
            __stcg(&h_out[(size_t)bq[q] * HH + jc[q]], (1.0f - z) * n + z * hpv[q]);
        }

        if (t != TT - 1) grid_barrier();
    }
#undef LOADH
#undef GRU_BODY
}

// ---------------------------------------------------------------------------
extern "C" void kernel_launch(void* const* d_in, const int* in_sizes, int n_in,
                              void* d_out, int out_size) {
    const float* x    = (const float*)d_in[0];
    const float* W_zx = (const float*)d_in[1];
    const float* W_zh = (const float*)d_in[2];
    const float* W_rx = (const float*)d_in[3];
    const float* W_rh = (const float*)d_in[4];
    const float* W_nx = (const float*)d_in[5];
    const float* W_nh = (const float*)d_in[6];
    const float* b_zx = (const float*)d_in[7];
    const float* b_zh = (const float*)d_in[8];
    const float* b_rx = (const float*)d_in[9];
    const float* b_rh = (const float*)d_in[10];
    const float* b_nx = (const float*)d_in[11];
    const float* b_nh = (const float*)d_in[12];
    float* out = (float*)d_out;

    cudaFuncSetAttribute(gru_scan_kernel,
                         cudaFuncAttributeMaxDynamicSharedMemorySize, SMEM_BYTES);

    xproj_kernel<<<dim3((BB * TT) / 128, HH / 128, 3), 256>>>(
        x, W_zx, W_rx, W_nx, b_zx, b_rx, b_nx);

    gru_scan_kernel<<<NCTA, NTHR, SMEM_BYTES>>>(
        out, W_zh, W_rh, W_nh, b_zh, b_rh, b_nh);
}

// round 11
// speedup vs baseline: 1.7542x; 1.1243x over previous
#include <cuda_runtime.h>
#include <math.h>

#define BB 64
#define TT 512
#define DD 512
#define HH 1024

#define NCTA 128
#define NTHR 256
#define JB   8

#define NRCH 16                      // rows per staged chunk
#define NCHR (BB / NRCH)             // 4 chunks per step
#define HRS  1028                    // staged row stride (floats), 16B-multiple
#define HBUF_FLOATS (NRCH * HRS)     // 16448 per buffer

// partials: [g][w][b][j] = 3*8*64*8 floats (48 KB)
#define PART_FLOATS (3 * 8 * BB * JB)
#define SMEM_FLOATS (PART_FLOATS + 2 * HBUF_FLOATS)
#define SMEM_BYTES (SMEM_FLOATS * 4)

typedef unsigned long long u64;

// Scratch (static device globals — allocation-free kernel_launch)
__device__ float g_XG[3 * TT * BB * HH];   // [g][t][b][h] x-projections (+ input bias)
__device__ float g_h[2][BB * HH];          // ping-pong hidden state
__device__ unsigned int g_bar_count = 0;
__device__ unsigned int g_bar_gen = 0;

__device__ __forceinline__ void ffma2(u64& d, u64 a, u64 b) {
    asm("fma.rn.f32x2 %0, %1, %2, %0;" : "+l"(d) : "l"(a), "l"(b));
}
__device__ __forceinline__ float pairsum(u64 v) {
    return __uint_as_float((unsigned)(v & 0xffffffffull)) +
           __uint_as_float((unsigned)(v >> 32));
}
__device__ __forceinline__ u64 pack2(float lo, float hi) {
    u64 r;
    asm("mov.b64 %0, {%1, %2};" : "=l"(r) : "f"(lo), "f"(hi));
    return r;
}
__device__ __forceinline__ u64 splat2(float a) {
    u64 r;
    asm("mov.b64 %0, {%1, %1};" : "=l"(r) : "f"(a));
    return r;
}
__device__ __forceinline__ unsigned smem_u32(const void* p) {
    return (unsigned)__cvta_generic_to_shared(p);
}
// 16B async copy global->smem, L1-bypass (.cg) — h produced by other SMs.
__device__ __forceinline__ void cp_async16(unsigned dst, const void* src) {
    asm volatile("cp.async.cg.shared.global [%0], [%1], 16;" :: "r"(dst), "l"(src));
}
__device__ __forceinline__ void cp_commit() {
    asm volatile("cp.async.commit_group;");
}
template <int N>
__device__ __forceinline__ void cp_wait() {
    asm volatile("cp.async.wait_group %0;" :: "n"(N));
}

// All 128 CTAs co-resident (1 CTA/SM) -> spin barrier safe. acq/rel semantics.
__device__ __forceinline__ void grid_barrier() {
    __syncthreads();
    if (threadIdx.x == 0) {
        unsigned gen;
        asm volatile("ld.relaxed.gpu.global.u32 %0, [%1];" : "=r"(gen) : "l"(&g_bar_gen));
        unsigned old;
        asm volatile("atom.acq_rel.gpu.global.add.u32 %0, [%1], 1;" : "=r"(old) : "l"(&g_bar_count));
        if (old == NCTA - 1) {
            asm volatile("st.relaxed.gpu.global.u32 [%0], %1;" :: "l"(&g_bar_count), "r"(0u));
            asm volatile("st.release.gpu.global.u32 [%0], %1;" :: "l"(&g_bar_gen), "r"(gen + 1));
        } else {
            unsigned cur;
            do {
                asm volatile("ld.acquire.gpu.global.u32 %0, [%1];" : "=r"(cur) : "l"(&g_bar_gen));
            } while (cur == gen);
        }
    }
    __syncthreads();
}

// ---------------------------------------------------------------------------
// Precompute xg[g][t][b][:] = x[b][t][:] @ W_gx + b_gx  (128x128x16, FFMA2)
// ---------------------------------------------------------------------------
__global__ __launch_bounds__(256) void xproj_kernel(
    const float* __restrict__ x,
    const float* __restrict__ Wz, const float* __restrict__ Wr, const float* __restrict__ Wn,
    const float* __restrict__ bz, const float* __restrict__ br, const float* __restrict__ bn) {

    int g = blockIdx.z;
    const float* Wm   = (g == 0) ? Wz : ((g == 1) ? Wr : Wn);
    const float* bias = (g == 0) ? bz : ((g == 1) ? br : bn);

    __shared__ float As[16][128];   // [k][m]
    __shared__ float Bs[16][128];   // [k][n]

    int m0 = blockIdx.x * 128;
    int n0 = blockIdx.y * 128;
    int tid = threadIdx.x;
    int txq = tid % 16, tyq = tid / 16;

    u64 acc2[4][8];
#pragma unroll
    for (int i = 0; i < 4; i++)
#pragma unroll
        for (int j = 0; j < 8; j++) acc2[i][j] = 0ull;

    for (int k0 = 0; k0 < DD; k0 += 16) {
#pragma unroll
        for (int l = 0; l < 2; l++) {
            int idx = tid + l * 256;
            int row = idx >> 2;
            int kk  = (idx & 3) * 4;
            float4 v = *(const float4*)&x[(size_t)(m0 + row) * DD + k0 + kk];
            As[kk + 0][row] = v.x;
            As[kk + 1][row] = v.y;
            As[kk + 2][row] = v.z;
            As[kk + 3][row] = v.w;
        }
#pragma unroll
        for (int l = 0; l < 2; l++) {
            int idx = tid + l * 256;
            int row = idx >> 5;
            int nn  = (idx & 31) * 4;
            *(float4*)&Bs[row][nn] = *(const float4*)&Wm[(size_t)(k0 + row) * HH + n0 + nn];
        }
        __syncthreads();
#pragma unroll
        for (int k = 0; k < 16; k++) {
            const u64* Ap = (const u64*)&As[k][tyq * 8];
            u64 ap0 = Ap[0], ap1 = Ap[1], ap2 = Ap[2], ap3 = Ap[3];
            float4 b0 = *(const float4*)&Bs[k][txq * 8];
            float4 b1 = *(const float4*)&Bs[k][txq * 8 + 4];
            u64 bs[8];
            bs[0] = splat2(b0.x); bs[1] = splat2(b0.y); bs[2] = splat2(b0.z); bs[3] = splat2(b0.w);
            bs[4] = splat2(b1.x); bs[5] = splat2(b1.y); bs[6] = splat2(b1.z); bs[7] = splat2(b1.w);
#pragma unroll
            for (int j = 0; j < 8; j++) {
                ffma2(acc2[0][j], ap0, bs[j]);
                ffma2(acc2[1][j], ap1, bs[j]);
                ffma2(acc2[2][j], ap2, bs[j]);
                ffma2(acc2[3][j], ap3, bs[j]);
            }
        }
        __syncthreads();
    }

#pragma unroll
    for (int ip = 0; ip < 4; ip++) {
#pragma unroll
        for (int half = 0; half < 2; half++) {
            int m  = m0 + tyq * 8 + ip * 2 + half;
            int bbv = m / TT;
            int tt = m % TT;
            float* outr = &g_XG[(((size_t)g * TT + tt) * BB + bbv) * HH + n0 + txq * 8];
#pragma unroll
            for (int j = 0; j < 8; j++) {
                u64 v = acc2[ip][j];
                float f = half ? __uint_as_float((unsigned)(v >> 32))
                               : __uint_as_float((unsigned)(v & 0xffffffffull));
                outr[j] = f + bias[n0 + txq * 8 + j];
            }
        }
    }
}

// ---------------------------------------------------------------------------
// Persistent GRU scan: register-resident W + cp.async row-chunk h staging.
// 128 CTAs x 8 j-cols. Warp w owns k[128w,128w+128); lane=(j=l&7, ksub=l>>3).
// Thread holds W[3][32k] in 48 u64 regs. h staged 16 rows x 1024 k per chunk,
// double-buffered; inner loop reads h via broadcast LDS.128 (29-cyc latency).
// ---------------------------------------------------------------------------
__global__ __launch_bounds__(NTHR, 1) void gru_scan_kernel(
    float* __restrict__ out,
    const float* __restrict__ Wzh, const float* __restrict__ Wrh, const float* __restrict__ Wnh,
    const float* __restrict__ bzh, const float* __restrict__ brh, const float* __restrict__ bnh)
{
    extern __shared__ float smem[];
    float* part = smem;                      // [g][w][b][j]: g*4096 + w*512 + b*8 + j
    float* hbuf0 = smem + PART_FLOATS;
    float* hbuf1 = hbuf0 + HBUF_FLOATS;

    const int tid  = threadIdx.x;
    const int jbk  = blockIdx.x;
    const int warp = tid >> 5;
    const int lane = tid & 31;
    const int jl   = lane & 7;
    const int ksub = lane >> 3;                 // 0..3
    const int kb   = warp * 128 + ksub * 32;    // thread's k-base (32 k's)
    const int pbase = warp * 512 + jl;          // partial store base

    // ---- W into registers: 16 pairs x 3 gates (held for all 512 steps) ----
    u64 wz[16], wr[16], wn[16];
    {
        const int jcolw = jbk * JB + jl;
#pragma unroll
        for (int p = 0; p < 16; p++) {
            int k = kb + 2 * p;
            wz[p] = pack2(__ldg(&Wzh[(size_t)k * HH + jcolw]), __ldg(&Wzh[(size_t)(k + 1) * HH + jcolw]));
            wr[p] = pack2(__ldg(&Wrh[(size_t)k * HH + jcolw]), __ldg(&Wrh[(size_t)(k + 1) * HH + jcolw]));
            wn[p] = pack2(__ldg(&Wnh[(size_t)k * HH + jcolw]), __ldg(&Wnh[(size_t)(k + 1) * HH + jcolw]));
        }
    }

    // ---- epilogue constants: thread handles output pairs tid, tid+256 ----
    int bq[2], jq[2], jc[2];
    float bzv[2], brv[2], bnv[2];
#pragma unroll
    for (int q = 0; q < 2; q++) {
        int p = tid + q * 256;
        bq[q] = p >> 3;
        jq[q] = p & 7;
        jc[q] = jbk * JB + jq[q];
        bzv[q] = __ldg(&bzh[jc[q]]);
        brv[q] = __ldg(&brh[jc[q]]);
        bnv[q] = __ldg(&bnh[jc[q]]);
    }

    // ---- zero h[0] (disjoint slices) ----
    for (int e = tid; e < (BB * HH) / NCTA; e += NTHR)
        g_h[0][blockIdx.x * ((BB * HH) / NCTA) + e] = 0.0f;
    grid_barrier();

    // staging: chunk = 16 rows x 1024 floats = 4096 float4; thread copies 16.
    // idx = tid + l*256 in [0,4096): row = idx>>8 (0..15), col4 = idx&255.
#define STAGE(BUF, CH) do {                                                        \
        float* buf_ = (BUF);                                                       \
        const float* hsrc_ = h_in + (size_t)((CH) * NRCH) * HH;                    \
        _Pragma("unroll")                                                          \
        for (int l_ = 0; l_ < 16; l_++) {                                          \
            int idx_ = tid + l_ * NTHR;                                            \
            int row_ = idx_ >> 8;                                                  \
            int col_ = (idx_ & 255) * 4;                                           \
            cp_async16(smem_u32(&buf_[row_ * HRS + col_]),                         \
                       &hsrc_[(size_t)row_ * HH + col_]);                          \
        }                                                                          \
        cp_commit();                                                               \
    } while (0)

#define LDSROW(BUF, SRC, LR) do {                                                  \
        const float4* hp4_ = (const float4*)((SRC) + (LR) * HRS + kb);             \
        _Pragma("unroll")                                                          \
        for (int i_ = 0; i_ < 8; i_++) (BUF)[i_] = hp4_[i_];                       \
    } while (0)

#define GRU_BODY(BUF, BV) do {                                                     \
        u64 az_ = 0, ar_ = 0, an_ = 0;                                             \
        const u64* hp_ = (const u64*)(BUF);                                        \
        _Pragma("unroll")                                                          \
        for (int p_ = 0; p_ < 16; p_++) {                                          \
            ffma2(az_, hp_[p_], wz[p_]);                                           \
            ffma2(ar_, hp_[p_], wr[p_]);                                           \
            ffma2(an_, hp_[p_], wn[p_]);                                           \
        }                                                                          \
        float zz_ = pairsum(az_), rr_ = pairsum(ar_), nn_ = pairsum(an_);          \
        zz_ += __shfl_xor_sync(0xffffffffu, zz_, 8);                               \
        zz_ += __shfl_xor_sync(0xffffffffu, zz_, 16);                              \
        rr_ += __shfl_xor_sync(0xffffffffu, rr_, 8);                               \
        rr_ += __shfl_xor_sync(0xffffffffu, rr_, 16);                              \
        nn_ += __shfl_xor_sync(0xffffffffu, nn_, 8);                               \
        nn_ += __shfl_xor_sync(0xffffffffu, nn_, 16);                              \
        if (ksub == 0) {                                                           \
            part[pbase + (BV) * 8]        = zz_;                                   \
            part[pbase + (BV) * 8 + 4096] = rr_;                                   \
            part[pbase + (BV) * 8 + 8192] = nn_;                                   \
        }                                                                          \
    } while (0)

    for (int t = 0; t < TT; t++) {
        const float* __restrict__ h_in  = g_h[t & 1];
        float* __restrict__ h_out = (t == TT - 1) ? out : g_h[(t + 1) & 1];

        // epilogue operand prefetch (consumed after the row loop)
        const float* xz = g_XG + ((size_t)(0 * TT + t)) * (BB * HH);
        const float* xr = g_XG + ((size_t)(1 * TT + t)) * (BB * HH);
        const float* xn = g_XG + ((size_t)(2 * TT + t)) * (BB * HH);
        float xzp[2], xrp[2], xnp[2], hpv[2];
#pragma unroll
        for (int q = 0; q < 2; q++) {
            xzp[q] = __ldg(&xz[(size_t)bq[q] * HH + jc[q]]);
            xrp[q] = __ldg(&xr[(size_t)bq[q] * HH + jc[q]]);
            xnp[q] = __ldg(&xn[(size_t)bq[q] * HH + jc[q]]);
            hpv[q] = __ldcg(&h_in[(size_t)bq[q] * HH + jc[q]]);
        }

        // prologue: stage chunk 0
        STAGE(hbuf0, 0);

        for (int ch = 0; ch < NCHR; ch++) {
            float* cur = (ch & 1) ? hbuf1 : hbuf0;
            if (ch + 1 < NCHR) {
                STAGE(((ch + 1) & 1) ? hbuf1 : hbuf0, ch + 1);
                cp_wait<1>();
            } else {
                cp_wait<0>();
            }
            __syncthreads();     // chunk ch visible to all threads

            // consume 16 rows, software-pipelined LDS by 2
            float4 bufA[8], bufB[8];
            LDSROW(bufA, cur, 0);
#pragma unroll
            for (int r = 0; r < NRCH; r += 2) {
                LDSROW(bufB, cur, r + 1);
                GRU_BODY(bufA, ch * NRCH + r);
                if (r + 2 < NRCH) LDSROW(bufA, cur, r + 2);
                GRU_BODY(bufB, ch * NRCH + r + 1);
            }
            __syncthreads();     // cur free for the chunk after next
        }

        // ---- cross-warp reduce + gate epilogue (2 outputs per thread) ----
#pragma unroll
        for (int q = 0; q < 2; q++) {
            int o = bq[q] * 8 + jq[q];
            float sz = 0.0f, sr = 0.0f, sn = 0.0f;
#pragma unroll
            for (int w = 0; w < 8; w++) {
                sz += part[w * 512 + o];
                sr += part[4096 + w * 512 + o];
                sn += part[8192 + w * 512 + o];
            }
            float z = 1.0f / (1.0f + __expf(-(xzp[q] + sz + bzv[q])));
            float r = 1.0f / (1.0f + __expf(-(xrp[q] + sr + brv[q])));
            float n = tanhf(xnp[q] + r * (sn + bnv[q]));
            __stcg(&h_out[(size_t)bq[q] * HH + jc[q]], (1.0f - z) * n + z * hpv[q]);
        }

        if (t != TT - 1) grid_barrier();
    }
#undef STAGE
#undef LDSROW
#undef GRU_BODY
}

// ---------------------------------------------------------------------------
extern "C" void kernel_launch(void* const* d_in, const int* in_sizes, int n_in,
                              void* d_out, int out_size) {
    const float* x    = (const float*)d_in[0];
    const float* W_zx = (const float*)d_in[1];
    const float* W_zh = (const float*)d_in[2];
    const float* W_rx = (const float*)d_in[3];
    const float* W_rh = (const float*)d_in[4];
    const float* W_nx = (const float*)d_in[5];
    const float* W_nh = (const float*)d_in[6];
    const float* b_zx = (const float*)d_in[7];
    const float* b_zh = (const float*)d_in[8];
    const float* b_rx = (const float*)d_in[9];
    const float* b_rh = (const float*)d_in[10];
    const float* b_nx = (const float*)d_in[11];
    const float* b_nh = (const float*)d_in[12];
    float* out = (float*)d_out;

    cudaFuncSetAttribute(gru_scan_kernel,
                         cudaFuncAttributeMaxDynamicSharedMemorySize, SMEM_BYTES);

    xproj_kernel<<<dim3((BB * TT) / 128, HH / 128, 3), 256>>>(
        x, W_zx, W_rx, W_nx, b_zx, b_rx, b_nx);

    gru_scan_kernel<<<NCTA, NTHR, SMEM_BYTES>>>(
        out, W_zh, W_rh, W_nh, b_zh, b_rh, b_nh);
}

// round 12
// speedup vs baseline: 1.8145x; 1.0344x over previous
#include <cuda_runtime.h>
#include <math.h>

#define BB 64
#define TT 512
#define DD 512
#define HH 1024

#define NCTA 128
#define NTHR 256
#define JB   8

#define NRCH 16                      // rows per staged chunk
#define NCHR (BB / NRCH)             // 4 chunks per step
#define HRS  1028                    // staged row stride (floats), 16B-multiple
#define HBUF_FLOATS (NRCH * HRS)     // 16448 per buffer

// partials: [g][w][b][j] = 3*8*64*8 floats (48 KB)
#define PART_FLOATS (3 * 8 * BB * JB)
#define SMEM_FLOATS (PART_FLOATS + 2 * HBUF_FLOATS)
#define SMEM_BYTES (SMEM_FLOATS * 4)

typedef unsigned long long u64;

// Scratch (static device globals — allocation-free kernel_launch)
__device__ float g_XG[3 * TT * BB * HH];   // [g][t][b][h] x-projections (+ input bias)
__device__ float g_h[2][BB * HH];          // ping-pong hidden state
__device__ unsigned int g_bar_count = 0;
__device__ unsigned int g_bar_gen = 0;

__device__ __forceinline__ void ffma2(u64& d, u64 a, u64 b) {
    asm("fma.rn.f32x2 %0, %1, %2, %0;" : "+l"(d) : "l"(a), "l"(b));
}
__device__ __forceinline__ float pairsum(u64 v) {
    return __uint_as_float((unsigned)(v & 0xffffffffull)) +
           __uint_as_float((unsigned)(v >> 32));
}
__device__ __forceinline__ u64 pack2(float lo, float hi) {
    u64 r;
    asm("mov.b64 %0, {%1, %2};" : "=l"(r) : "f"(lo), "f"(hi));
    return r;
}
__device__ __forceinline__ u64 splat2(float a) {
    u64 r;
    asm("mov.b64 %0, {%1, %1};" : "=l"(r) : "f"(a));
    return r;
}
__device__ __forceinline__ unsigned smem_u32(const void* p) {
    return (unsigned)__cvta_generic_to_shared(p);
}
// 16B async copy global->smem, L1-bypass (.cg) — h produced by other SMs.
__device__ __forceinline__ void cp_async16(unsigned dst, const void* src) {
    asm volatile("cp.async.cg.shared.global [%0], [%1], 16;" :: "r"(dst), "l"(src));
}
__device__ __forceinline__ void cp_commit() {
    asm volatile("cp.async.commit_group;");
}
template <int N>
__device__ __forceinline__ void cp_wait() {
    asm volatile("cp.async.wait_group %0;" :: "n"(N));
}

// All 128 CTAs co-resident (1 CTA/SM) -> spin barrier safe. acq/rel semantics.
__device__ __forceinline__ void grid_barrier() {
    __syncthreads();
    if (threadIdx.x == 0) {
        unsigned gen;
        asm volatile("ld.relaxed.gpu.global.u32 %0, [%1];" : "=r"(gen) : "l"(&g_bar_gen));
        unsigned old;
        asm volatile("atom.acq_rel.gpu.global.add.u32 %0, [%1], 1;" : "=r"(old) : "l"(&g_bar_count));
        if (old == NCTA - 1) {
            asm volatile("st.relaxed.gpu.global.u32 [%0], %1;" :: "l"(&g_bar_count), "r"(0u));
            asm volatile("st.release.gpu.global.u32 [%0], %1;" :: "l"(&g_bar_gen), "r"(gen + 1));
        } else {
            unsigned cur;
            do {
                asm volatile("ld.acquire.gpu.global.u32 %0, [%1];" : "=r"(cur) : "l"(&g_bar_gen));
            } while (cur == gen);
        }
    }
    __syncthreads();
}

// ---------------------------------------------------------------------------
// Precompute xg[g][t][b][:] = x[b][t][:] @ W_gx + b_gx  (128x128x16, FFMA2)
// ---------------------------------------------------------------------------
__global__ __launch_bounds__(256) void xproj_kernel(
    const float* __restrict__ x,
    const float* __restrict__ Wz, const float* __restrict__ Wr, const float* __restrict__ Wn,
    const float* __restrict__ bz, const float* __restrict__ br, const float* __restrict__ bn) {

    int g = blockIdx.z;
    const float* Wm   = (g == 0) ? Wz : ((g == 1) ? Wr : Wn);
    const float* bias = (g == 0) ? bz : ((g == 1) ? br : bn);

    __shared__ float As[16][128];   // [k][m]
    __shared__ float Bs[16][128];   // [k][n]

    int m0 = blockIdx.x * 128;
    int n0 = blockIdx.y * 128;
    int tid = threadIdx.x;
    int txq = tid % 16, tyq = tid / 16;

    u64 acc2[4][8];
#pragma unroll
    for (int i = 0; i < 4; i++)
#pragma unroll
        for (int j = 0; j < 8; j++) acc2[i][j] = 0ull;

    for (int k0 = 0; k0 < DD; k0 += 16) {
#pragma unroll
        for (int l = 0; l < 2; l++) {
            int idx = tid + l * 256;
            int row = idx >> 2;
            int kk  = (idx & 3) * 4;
            float4 v = *(const float4*)&x[(size_t)(m0 + row) * DD + k0 + kk];
            As[kk + 0][row] = v.x;
            As[kk + 1][row] = v.y;
            As[kk + 2][row] = v.z;
            As[kk + 3][row] = v.w;
        }
#pragma unroll
        for (int l = 0; l < 2; l++) {
            int idx = tid + l * 256;
            int row = idx >> 5;
            int nn  = (idx & 31) * 4;
            *(float4*)&Bs[row][nn] = *(const float4*)&Wm[(size_t)(k0 + row) * HH + n0 + nn];
        }
        __syncthreads();
#pragma unroll
        for (int k = 0; k < 16; k++) {
            const u64* Ap = (const u64*)&As[k][tyq * 8];
            u64 ap0 = Ap[0], ap1 = Ap[1], ap2 = Ap[2], ap3 = Ap[3];
            float4 b0 = *(const float4*)&Bs[k][txq * 8];
            float4 b1 = *(const float4*)&Bs[k][txq * 8 + 4];
            u64 bs[8];
            bs[0] = splat2(b0.x); bs[1] = splat2(b0.y); bs[2] = splat2(b0.z); bs[3] = splat2(b0.w);
            bs[4] = splat2(b1.x); bs[5] = splat2(b1.y); bs[6] = splat2(b1.z); bs[7] = splat2(b1.w);
#pragma unroll
            for (int j = 0; j < 8; j++) {
                ffma2(acc2[0][j], ap0, bs[j]);
                ffma2(acc2[1][j], ap1, bs[j]);
                ffma2(acc2[2][j], ap2, bs[j]);
                ffma2(acc2[3][j], ap3, bs[j]);
            }
        }
        __syncthreads();
    }

#pragma unroll
    for (int ip = 0; ip < 4; ip++) {
#pragma unroll
        for (int half = 0; half < 2; half++) {
            int m  = m0 + tyq * 8 + ip * 2 + half;
            int bbv = m / TT;
            int tt = m % TT;
            float* outr = &g_XG[(((size_t)g * TT + tt) * BB + bbv) * HH + n0 + txq * 8];
#pragma unroll
            for (int j = 0; j < 8; j++) {
                u64 v = acc2[ip][j];
                float f = half ? __uint_as_float((unsigned)(v >> 32))
                               : __uint_as_float((unsigned)(v & 0xffffffffull));
                outr[j] = f + bias[n0 + txq * 8 + j];
            }
        }
    }
}

// ---------------------------------------------------------------------------
// Persistent GRU scan: register-resident W + cp.async row-chunk h staging.
// 128 CTAs x 8 j-cols. Warp w owns k[128w,128w+128); lane=(j=l&7, ksub=l>>3).
// CONFLICT-FREE k interleave: ksub s owns float4-chunks {s, s+4, ..., s+28}
// of the warp's 128-k slice, so the 4 s-lanes of an LDS.128 hit adjacent
// 16B chunks (different banks) instead of 128B-strided (same bank, 4-way).
// W regs are loaded in the matching permuted order; reduction unchanged.
// ---------------------------------------------------------------------------
__global__ __launch_bounds__(NTHR, 1) void gru_scan_kernel(
    float* __restrict__ out,
    const float* __restrict__ Wzh, const float* __restrict__ Wrh, const float* __restrict__ Wnh,
    const float* __restrict__ bzh, const float* __restrict__ brh, const float* __restrict__ bnh)
{
    extern __shared__ float smem[];
    float* part = smem;                      // [g][w][b][j]: g*4096 + w*512 + b*8 + j
    float* hbuf0 = smem + PART_FLOATS;
    float* hbuf1 = hbuf0 + HBUF_FLOATS;

    const int tid  = threadIdx.x;
    const int jbk  = blockIdx.x;
    const int warp = tid >> 5;
    const int lane = tid & 31;
    const int jl   = lane & 7;
    const int ksub = lane >> 3;                 // 0..3
    const int kwb  = warp * 128;                // warp's k-slice base
    const int pbase = warp * 512 + jl;          // partial store base

    // ---- W into registers, permuted k order (held for all 512 steps) ----
    // pair p (=2i+half): k = kwb + (ksub + 4i)*4 + half*2
    u64 wz[16], wr[16], wn[16];
    {
        const int jcolw = jbk * JB + jl;
#pragma unroll
        for (int p = 0; p < 16; p++) {
            int i    = p >> 1;
            int half = p & 1;
            int k    = kwb + (ksub + 4 * i) * 4 + half * 2;
            wz[p] = pack2(__ldg(&Wzh[(size_t)k * HH + jcolw]), __ldg(&Wzh[(size_t)(k + 1) * HH + jcolw]));
            wr[p] = pack2(__ldg(&Wrh[(size_t)k * HH + jcolw]), __ldg(&Wrh[(size_t)(k + 1) * HH + jcolw]));
            wn[p] = pack2(__ldg(&Wnh[(size_t)k * HH + jcolw]), __ldg(&Wnh[(size_t)(k + 1) * HH + jcolw]));
        }
    }

    // ---- epilogue constants: thread handles output pairs tid, tid+256 ----
    int bq[2], jq[2], jc[2];
    float bzv[2], brv[2], bnv[2];
#pragma unroll
    for (int q = 0; q < 2; q++) {
        int p = tid + q * 256;
        bq[q] = p >> 3;
        jq[q] = p & 7;
        jc[q] = jbk * JB + jq[q];
        bzv[q] = __ldg(&bzh[jc[q]]);
        brv[q] = __ldg(&brh[jc[q]]);
        bnv[q] = __ldg(&bnh[jc[q]]);
    }

    // ---- zero h[0] (disjoint slices) ----
    for (int e = tid; e < (BB * HH) / NCTA; e += NTHR)
        g_h[0][blockIdx.x * ((BB * HH) / NCTA) + e] = 0.0f;
    grid_barrier();

    // staging: chunk = 16 rows x 1024 floats = 4096 float4; thread copies 16.
    // idx = tid + l*256 in [0,4096): row = idx>>8 (0..15), col4 = idx&255.
#define STAGE(BUF, CH) do {                                                        \
        float* buf_ = (BUF);                                                       \
        const float* hsrc_ = h_in + (size_t)((CH) * NRCH) * HH;                    \
        _Pragma("unroll")                                                          \
        for (int l_ = 0; l_ < 16; l_++) {                                          \
            int idx_ = tid + l_ * NTHR;                                            \
            int row_ = idx_ >> 8;                                                  \
            int col_ = (idx_ & 255) * 4;                                           \
            cp_async16(smem_u32(&buf_[row_ * HRS + col_]),                         \
                       &hsrc_[(size_t)row_ * HH + col_]);                          \
        }                                                                          \
        cp_commit();                                                               \
    } while (0)

    // conflict-free: 4 s-lanes read adjacent float4s (16B apart), 8 j broadcast
#define LDSROW(BUF, SRC, LR) do {                                                  \
        const float4* hp4_ = (const float4*)((SRC) + (LR) * HRS + kwb);            \
        _Pragma("unroll")                                                          \
        for (int i_ = 0; i_ < 8; i_++) (BUF)[i_] = hp4_[ksub + 4 * i_];            \
    } while (0)

#define GRU_BODY(BUF, BV) do {                                                     \
        u64 az_ = 0, ar_ = 0, an_ = 0;                                             \
        const u64* hp_ = (const u64*)(BUF);                                        \
        _Pragma("unroll")                                                          \
        for (int p_ = 0; p_ < 16; p_++) {                                          \
            ffma2(az_, hp_[p_], wz[p_]);                                           \
            ffma2(ar_, hp_[p_], wr[p_]);                                           \
            ffma2(an_, hp_[p_], wn[p_]);                                           \
        }                                                                          \
        float zz_ = pairsum(az_), rr_ = pairsum(ar_), nn_ = pairsum(an_);          \
        zz_ += __shfl_xor_sync(0xffffffffu, zz_, 8);                               \
        zz_ += __shfl_xor_sync(0xffffffffu, zz_, 16);                              \
        rr_ += __shfl_xor_sync(0xffffffffu, rr_, 8);                               \
        rr_ += __shfl_xor_sync(0xffffffffu, rr_, 16);                              \
        nn_ += __shfl_xor_sync(0xffffffffu, nn_, 8);                               \
        nn_ += __shfl_xor_sync(0xffffffffu, nn_, 16);                              \
        if (ksub == 0) {                                                           \
            part[pbase + (BV) * 8]        = zz_;                                   \
            part[pbase + (BV) * 8 + 4096] = rr_;                                   \
            part[pbase + (BV) * 8 + 8192] = nn_;                                   \
        }                                                                          \
    } while (0)

    for (int t = 0; t < TT; t++) {
        const float* __restrict__ h_in  = g_h[t & 1];
        float* __restrict__ h_out = (t == TT - 1) ? out : g_h[(t + 1) & 1];

        // epilogue operand prefetch (consumed after the row loop)
        const float* xz = g_XG + ((size_t)(0 * TT + t)) * (BB * HH);
        const float* xr = g_XG + ((size_t)(1 * TT + t)) * (BB * HH);
        const float* xn = g_XG + ((size_t)(2 * TT + t)) * (BB * HH);
        float xzp[2], xrp[2], xnp[2], hpv[2];
#pragma unroll
        for (int q = 0; q < 2; q++) {
            xzp[q] = __ldg(&xz[(size_t)bq[q] * HH + jc[q]]);
            xrp[q] = __ldg(&xr[(size_t)bq[q] * HH + jc[q]]);
            xnp[q] = __ldg(&xn[(size_t)bq[q] * HH + jc[q]]);
            hpv[q] = __ldcg(&h_in[(size_t)bq[q] * HH + jc[q]]);
        }

        // prologue: stage chunk 0
        STAGE(hbuf0, 0);

        for (int ch = 0; ch < NCHR; ch++) {
            float* cur = (ch & 1) ? hbuf1 : hbuf0;
            if (ch + 1 < NCHR) {
                STAGE(((ch + 1) & 1) ? hbuf1 : hbuf0, ch + 1);
                cp_wait<1>();
            } else {
                cp_wait<0>();
            }
            __syncthreads();     // chunk ch visible to all threads

            // consume 16 rows, software-pipelined LDS by 2
            float4 bufA[8], bufB[8];
            LDSROW(bufA, cur, 0);
#pragma unroll
            for (int r = 0; r < NRCH; r += 2) {
                LDSROW(bufB, cur, r + 1);
                GRU_BODY(bufA, ch * NRCH + r);
                if (r + 2 < NRCH) LDSROW(bufA, cur, r + 2);
                GRU_BODY(bufB, ch * NRCH + r + 1);
            }
            __syncthreads();     // cur free for the chunk after next
        }

        // ---- cross-warp reduce + gate epilogue (2 outputs per thread) ----
#pragma unroll
        for (int q = 0; q < 2; q++) {
            int o = bq[q] * 8 + jq[q];
            float sz = 0.0f, sr = 0.0f, sn = 0.0f;
#pragma unroll
            for (int w = 0; w < 8; w++) {
                sz += part[w * 512 + o];
                sr += part[4096 + w * 512 + o];
                sn += part[8192 + w * 512 + o];
            }
            float z = 1.0f / (1.0f + __expf(-(xzp[q] + sz + bzv[q])));
            float r = 1.0f / (1.0f + __expf(-(xrp[q] + sr + brv[q])));
            float n = tanhf(xnp[q] + r * (sn + bnv[q]));
            __stcg(&h_out[(size_t)bq[q] * HH + jc[q]], (1.0f - z) * n + z * hpv[q]);
        }

        if (t != TT - 1) grid_barrier();
    }
#undef STAGE
#undef LDSROW
#undef GRU_BODY
}

// ---------------------------------------------------------------------------
extern "C" void kernel_launch(void* const* d_in, const int* in_sizes, int n_in,
                              void* d_out, int out_size) {
    const float* x    = (const float*)d_in[0];
    const float* W_zx = (const float*)d_in[1];
    const float* W_zh = (const float*)d_in[2];
    const float* W_rx = (const float*)d_in[3];
    const float* W_rh = (const float*)d_in[4];
    const float* W_nx = (const float*)d_in[5];
    const float* W_nh = (const float*)d_in[6];
    const float* b_zx = (const float*)d_in[7];
    const float* b_zh = (const float*)d_in[8];
    const float* b_rx = (const float*)d_in[9];
    const float* b_rh = (const float*)d_in[10];
    const float* b_nx = (const float*)d_in[11];
    const float* b_nh = (const float*)d_in[12];
    float* out = (float*)d_out;

    cudaFuncSetAttribute(gru_scan_kernel,
                         cudaFuncAttributeMaxDynamicSharedMemorySize, SMEM_BYTES);

    xproj_kernel<<<dim3((BB * TT) / 128, HH / 128, 3), 256>>>(
        x, W_zx, W_rx, W_nx, b_zx, b_rx, b_nx);

    gru_scan_kernel<<<NCTA, NTHR, SMEM_BYTES>>>(
        out, W_zh, W_rh, W_nh, b_zh, b_rh, b_nh);
}